// round 10
// baseline (speedup 1.0000x reference)
#include <cuda_runtime.h>
#include <cuda_bf16.h>

// Problem constants (fixed by the reference)
#define Bq   4
#define Lq   100
#define Mq   2048
#define Eq   50
#define EX_SU_INV (1.0f / 1000.0f)
#define EX_TU_INV (1.0f / 86400.0f)

#define TM      128              // m-values per block tile (tail-balance axis: 512->256->128)
#define NCHUNK  (Mq / TM)        // 16
#define THREADS 416              // 13 warps; threads 0..399 active in mainloop
#define ACTIVE  400
#define WINM    32               // m per window
#define WINF    (WINM * Eq)      // 1600 floats per window = ACTIVE * 4
#define NITER   (TM / WINM)      // 4

__global__ __launch_bounds__(THREADS, 4)
void ctr_embedding_kernel(const int*   __restrict__ traj_location,  // [B,L]
                          const float* __restrict__ mat2,           // [NLOC,M]
                          const float* __restrict__ vector,         // [B,L]
                          const int*   __restrict__ traj_length,    // [B]
                          const float* __restrict__ emb_su,         // [2,E]
                          const float* __restrict__ emb_sl,
                          const float* __restrict__ emb_tu,
                          const float* __restrict__ emb_tl,
                          float*       __restrict__ out)            // [B,L,M,E]
{
    __shared__ float  s_ds[TM];   // gathered mat2 slice (or zeros)
    __shared__ float2 s_bs[Eq];   // (base[e], slope[e])

    const int bl    = blockIdx.x;          // 0 .. B*L-1
    const int chunk = blockIdx.y;          // 0 .. NCHUNK-1
    const int b     = bl / Lq;
    const int l     = bl - b * Lq;
    const int m0    = chunk * TM;
    const int tid   = threadIdx.x;

    const bool valid = (l < traj_length[b]);

    // Stage gathered mat2 slice (or zeros) into smem, coalesced.
    if (valid) {
        const int loc = traj_location[bl] - 1;          // 1-based -> 0-based
        const float* row = mat2 + (size_t)loc * Mq + m0;
        if (tid < TM) s_ds[tid] = row[tid];
    } else {
        if (tid < TM) s_ds[tid] = 0.0f;
    }

    // Precompute per-(b,l) base/slope vectors over E.
    if (tid < Eq) {
        const int off = (valid ? 1 : 0) * Eq + tid;
        const float dt = vector[bl];
        const float tl = emb_tl[off], tu = emb_tu[off];
        const float sl = emb_sl[off], su = emb_su[off];
        // time_interval = tl + (tu - tl) * dt / EX_TU   (EX_TL = 0)
        const float time_i = fmaf(tu - tl, dt * EX_TU_INV, tl);
        // space_interval = sl + (su - sl) * ds / EX_SU  (EX_SL = 0)
        s_bs[tid] = make_float2(sl + time_i, (su - sl) * EX_SU_INV);
    }
    __syncthreads();

    // Winner geometry: 1600 floats (= 32 m = 400 float4) per window.
    // Thread t < 400 always owns floats [4t, 4t+3] of every window, so its
    // e-phase (4t mod 50) is loop-invariant -> constants in registers.
    // A float4 crosses at most one m boundary; split-slope (sl_lo / sl_hi
    // with zeros) removes all SELs:
    //   r[j] = fma(sl_hi[j], d_hi, fma(sl_lo[j], d_lo, base[j])).
    // Inner loop: 2 broadcast LDS.32 + 8 FFMA + 1 STG.128, fully unrolled
    // over all 4 windows (front-batched LDS, high store MLP).
    if (tid < ACTIVE) {
        const int f    = 4 * tid;              // float offset in window
        const int m_lo = f / Eq;               // m (within window) of float f
        const int m_hi = (f + 3) / Eq;         // m of float f+3
        const int s    = Eq * (m_lo + 1) - f;  // first j using d_hi (>=4 => none)

        float base[4], sl_lo[4], sl_hi[4];
        #pragma unroll
        for (int j = 0; j < 4; j++) {
            const float2 c = s_bs[(f + j) % Eq];
            base[j]  = c.x;
            sl_lo[j] = (j < s) ? c.y : 0.0f;
            sl_hi[j] = c.y - sl_lo[j];
        }

        float* __restrict__ outp =
            out + ((size_t)bl * Mq + (size_t)m0) * Eq + f;

        #pragma unroll
        for (int w = 0; w < NITER; w++) {
            const int mb = w * WINM;
            const float d_lo = s_ds[mb + m_lo];
            const float d_hi = s_ds[mb + m_hi];
            float r[4];
            #pragma unroll
            for (int j = 0; j < 4; j++)
                r[j] = fmaf(sl_hi[j], d_hi, fmaf(sl_lo[j], d_lo, base[j]));

            // 128-bit store, evict-first (output stream >> L2).
            asm volatile(
                "st.global.cs.v4.f32 [%0], {%1,%2,%3,%4};"
                :: "l"(outp + (size_t)w * WINF),
                   "f"(r[0]), "f"(r[1]), "f"(r[2]), "f"(r[3])
                : "memory");
        }
    }
}

extern "C" void kernel_launch(void* const* d_in, const int* in_sizes, int n_in,
                              void* d_out, int out_size)
{
    const int*   traj_location = (const int*)  d_in[0];
    const float* mat2          = (const float*)d_in[1];
    const float* vector        = (const float*)d_in[2];
    const int*   traj_length   = (const int*)  d_in[3];
    const float* emb_su        = (const float*)d_in[4];
    const float* emb_sl        = (const float*)d_in[5];
    const float* emb_tu        = (const float*)d_in[6];
    const float* emb_tl        = (const float*)d_in[7];
    float* out = (float*)d_out;

    dim3 grid(Bq * Lq, NCHUNK);
    ctr_embedding_kernel<<<grid, THREADS>>>(traj_location, mat2, vector,
                                            traj_length, emb_su, emb_sl,
                                            emb_tu, emb_tl, out);
}

// round 11
// speedup vs baseline: 1.0715x; 1.0715x over previous
#include <cuda_runtime.h>
#include <cuda_bf16.h>

// Problem constants (fixed by the reference)
#define Bq   4
#define Lq   100
#define Mq   2048
#define Eq   50
#define EX_SU_INV (1.0f / 1000.0f)
#define EX_TU_INV (1.0f / 86400.0f)

#define TM      256              // m-values per block tile (R9 optimum)
#define NCHUNK  (Mq / TM)        // 8
#define THREADS 448              // 14 warps; threads 0..399 active in mainloop
#define ACTIVE  400
#define WINM    32               // m per window
#define WINF    (WINM * Eq)      // 1600 floats per window = ACTIVE * 4
#define NITER   (TM / WINM)      // 8

__global__ __launch_bounds__(THREADS, 4)
void ctr_embedding_kernel(const int*   __restrict__ traj_location,  // [B,L]
                          const float* __restrict__ mat2,           // [NLOC,M]
                          const float* __restrict__ vector,         // [B,L]
                          const int*   __restrict__ traj_length,    // [B]
                          const float* __restrict__ emb_su,         // [2,E]
                          const float* __restrict__ emb_sl,
                          const float* __restrict__ emb_tu,
                          const float* __restrict__ emb_tl,
                          float*       __restrict__ out)            // [B,L,M,E]
{
    __shared__ float  s_ds[TM];   // gathered mat2 slice (or zeros)
    __shared__ float2 s_bs[Eq];   // (base[e], slope[e])

    const int bl    = blockIdx.x;          // 0 .. B*L-1
    const int chunk = blockIdx.y;          // 0 .. NCHUNK-1
    const int b     = bl / Lq;
    const int l     = bl - b * Lq;
    const int m0    = chunk * TM;
    const int tid   = threadIdx.x;

    const bool valid = (l < traj_length[b]);

    // Stage gathered mat2 slice (or zeros) into smem with float4 loads:
    // 64 threads x LDG.128 covers TM=256 floats (mat2 rows are 8KB-aligned).
    if (tid < TM / 4) {
        float4 v = make_float4(0.f, 0.f, 0.f, 0.f);
        if (valid) {
            const int loc = traj_location[bl] - 1;      // 1-based -> 0-based
            v = ((const float4*)(mat2 + (size_t)loc * Mq + m0))[tid];
        }
        ((float4*)s_ds)[tid] = v;
    }

    // Precompute per-(b,l) base/slope vectors over E.
    if (tid >= 64 && tid < 64 + Eq) {       // different warps than the stagers
        const int e   = tid - 64;
        const int off = (valid ? 1 : 0) * Eq + e;
        const float dt = vector[bl];
        const float tl = emb_tl[off], tu = emb_tu[off];
        const float sl = emb_sl[off], su = emb_su[off];
        // time_interval = tl + (tu - tl) * dt / EX_TU   (EX_TL = 0)
        const float time_i = fmaf(tu - tl, dt * EX_TU_INV, tl);
        // space_interval = sl + (su - sl) * ds / EX_SU  (EX_SL = 0)
        s_bs[e] = make_float2(sl + time_i, (su - sl) * EX_SU_INV);
    }
    __syncthreads();

    // Winner geometry (R9): 1600 floats (= 32 m = 400 float4) per window.
    // Thread t < 400 always owns floats [4t, 4t+3] of every window, so its
    // e-phase (4t mod 50) is loop-invariant -> constants in registers.
    // A float4 crosses at most one m boundary; split-slope (sl_lo / sl_hi
    // with zeros) removes all SELs:
    //   r[j] = fma(sl_hi[j], d_hi, fma(sl_lo[j], d_lo, base[j])).
    // Inner loop: 2 broadcast LDS.32 + 8 FFMA + 1 STG.128, fully unrolled
    // over all 8 windows (front-batched LDS, high store MLP).
    if (tid < ACTIVE) {
        const int f    = 4 * tid;              // float offset in window
        const int m_lo = f / Eq;               // m (within window) of float f
        const int m_hi = (f + 3) / Eq;         // m of float f+3
        const int s    = Eq * (m_lo + 1) - f;  // first j using d_hi (>=4 => none)

        float base[4], sl_lo[4], sl_hi[4];
        #pragma unroll
        for (int j = 0; j < 4; j++) {
            const float2 c = s_bs[(f + j) % Eq];
            base[j]  = c.x;
            sl_lo[j] = (j < s) ? c.y : 0.0f;
            sl_hi[j] = c.y - sl_lo[j];
        }

        float* __restrict__ outp =
            out + ((size_t)bl * Mq + (size_t)m0) * Eq + f;

        #pragma unroll
        for (int w = 0; w < NITER; w++) {
            const int mb = w * WINM;
            const float d_lo = s_ds[mb + m_lo];
            const float d_hi = s_ds[mb + m_hi];
            float r[4];
            #pragma unroll
            for (int j = 0; j < 4; j++)
                r[j] = fmaf(sl_hi[j], d_hi, fmaf(sl_lo[j], d_lo, base[j]));

            // 128-bit store, evict-first (output stream >> L2).
            asm volatile(
                "st.global.cs.v4.f32 [%0], {%1,%2,%3,%4};"
                :: "l"(outp + (size_t)w * WINF),
                   "f"(r[0]), "f"(r[1]), "f"(r[2]), "f"(r[3])
                : "memory");
        }
    }
}

extern "C" void kernel_launch(void* const* d_in, const int* in_sizes, int n_in,
                              void* d_out, int out_size)
{
    const int*   traj_location = (const int*)  d_in[0];
    const float* mat2          = (const float*)d_in[1];
    const float* vector        = (const float*)d_in[2];
    const int*   traj_length   = (const int*)  d_in[3];
    const float* emb_su        = (const float*)d_in[4];
    const float* emb_sl        = (const float*)d_in[5];
    const float* emb_tu        = (const float*)d_in[6];
    const float* emb_tl        = (const float*)d_in[7];
    float* out = (float*)d_out;

    dim3 grid(Bq * Lq, NCHUNK);
    ctr_embedding_kernel<<<grid, THREADS>>>(traj_location, mat2, vector,
                                            traj_length, emb_su, emb_sl,
                                            emb_tu, emb_tl, out);
}